// round 2
// baseline (speedup 1.0000x reference)
#include <cuda_runtime.h>

#define QSZ 128
#define BATCH 4096

// ---------------- scratch (static device globals; no runtime allocation) ---------
__device__ float g_wc1[32 * 25];              // [o][ky*5+kx]
__device__ float g_wc2[32 * 64 * 25];         // [ci][o][ky*5+kx]  (transposed for staging)
__device__ float g_W3 [512 * 1024];           // [o][k]
__device__ float g_h1 [BATCH * 32 * 144];     // conv1 pooled+relu  [b][c][12*12]
__device__ float g_h2 [BATCH * 1024];         // conv2 pooled+relu flattened NCHW [b][c*16+py*4+px]
__device__ float g_h3 [BATCH * 512];          // fc1 relu

// ---------------- weight reconstruction (gather + sign) --------------------------
__global__ void build_weights(const int* __restrict__ hi1, const int* __restrict__ hi2,
                              const int* __restrict__ hi3,
                              const float* __restrict__ s1, const float* __restrict__ s2,
                              const float* __restrict__ s3,
                              const float* __restrict__ w1, const float* __restrict__ w2,
                              const float* __restrict__ w3)
{
    int idx = blockIdx.x * blockDim.x + threadIdx.x;
    if (idx < 800) {
        int o = idx / 25, m = idx % 25;
        g_wc1[idx] = w1[o * QSZ + hi1[m]] * s1[m];
    } else if (idx < 52000) {
        int j = idx - 800;
        int ci = j / 1600, r = j % 1600;
        int o = r / 25, m = r % 25;
        int s = ci * 25 + m;                       // source index into (64,800) reshape order
        g_wc2[j] = w2[o * QSZ + hi2[s]] * s2[s];
    } else if (idx < 52000 + 512 * 1024) {
        int j = idx - 52000;
        int o = j >> 10, k = j & 1023;
        g_W3[j] = w3[o * QSZ + hi3[k]] * s3[k];
    }
}

// ---------------- conv1 5x5 (1->32) + maxpool2 + relu ----------------------------
// block = one image. 256 threads: lane-channel mapping -> smem broadcast on input,
// stride-25 (conflict-free) on weights.
__global__ __launch_bounds__(256) void conv1_kernel(const float* __restrict__ x,
                                                    const float* __restrict__ b1)
{
    __shared__ float xs[784];
    __shared__ float ws[800];
    int b = blockIdx.x;
    int tid = threadIdx.x;
    for (int t = tid; t < 784; t += 256) xs[t] = x[b * 784 + t];
    for (int t = tid; t < 800; t += 256) ws[t] = g_wc1[t];
    __syncthreads();

    int o = tid & 31;        // output channel
    int pbase = tid >> 5;    // 0..7
    float w[25];
#pragma unroll
    for (int m = 0; m < 25; m++) w[m] = ws[o * 25 + m];
    float bias = b1[o];

#pragma unroll 1
    for (int it = 0; it < 18; it++) {
        int pos = pbase + it * 8;           // 0..143
        int py = pos / 12, px = pos % 12;
        int r0 = 2 * py, c0 = 2 * px;
        float p[36];
#pragma unroll
        for (int rr = 0; rr < 6; rr++)
#pragma unroll
            for (int cc = 0; cc < 6; cc++)
                p[rr * 6 + cc] = xs[(r0 + rr) * 28 + c0 + cc];
        float mx = -1e30f;
#pragma unroll
        for (int dy = 0; dy < 2; dy++)
#pragma unroll
            for (int dx = 0; dx < 2; dx++) {
                float a = 0.f;
#pragma unroll
                for (int ky = 0; ky < 5; ky++)
#pragma unroll
                    for (int kx = 0; kx < 5; kx++)
                        a = fmaf(p[(dy + ky) * 6 + dx + kx], w[ky * 5 + kx], a);
                mx = fmaxf(mx, a);
            }
        float v = mx + bias;
        g_h1[b * 4608 + o * 144 + pos] = v > 0.f ? v : 0.f;
    }
}

// ---------------- conv2 5x5 (32->64) + maxpool2 + relu ---------------------------
// block = one image. thread = (c_out = tid&63, pooled column pbase = tid>>6).
// Input tile in smem (broadcast reads), per-ci weight slice staged contiguously.
__global__ __launch_bounds__(256) void conv2_kernel(const float* __restrict__ b2)
{
    __shared__ float in_s[4608];    // 32 x 12 x 12
    __shared__ float ws[1600];      // 64 x 25, one input channel slice
    int b = blockIdx.x;
    int tid = threadIdx.x;
    for (int t = tid; t < 4608; t += 256) in_s[t] = g_h1[b * 4608 + t];

    int c_out = tid & 63;
    int pbase = tid >> 6;           // pooled px, 0..3
    float acc[4][4];
#pragma unroll
    for (int i = 0; i < 4; i++)
#pragma unroll
        for (int j = 0; j < 4; j++) acc[i][j] = 0.f;

    for (int ci = 0; ci < 32; ci++) {
        __syncthreads();            // prior compute done (and on ci=0: in_s staged)
#pragma unroll
        for (int t = 0; t < 7; t++) {
            int e = tid + t * 256;
            if (e < 1600) ws[e] = g_wc2[ci * 1600 + e];
        }
        __syncthreads();

        float w[25];
#pragma unroll
        for (int m = 0; m < 25; m++) w[m] = ws[c_out * 25 + m];
        const float* in_ci = in_s + ci * 144;

#pragma unroll
        for (int it = 0; it < 4; it++) {       // pooled row py = it
            int r0 = 2 * it, c0 = 2 * pbase;
            float p[36];
#pragma unroll
            for (int rr = 0; rr < 6; rr++)
#pragma unroll
                for (int cc = 0; cc < 6; cc++)
                    p[rr * 6 + cc] = in_ci[(r0 + rr) * 12 + c0 + cc];
#pragma unroll
            for (int dy = 0; dy < 2; dy++)
#pragma unroll
                for (int dx = 0; dx < 2; dx++) {
                    float a = 0.f;
#pragma unroll
                    for (int ky = 0; ky < 5; ky++)
#pragma unroll
                        for (int kx = 0; kx < 5; kx++)
                            a = fmaf(p[(dy + ky) * 6 + dx + kx], w[ky * 5 + kx], a);
                    acc[it][dy * 2 + dx] += a;
                }
        }
    }

    float bias = b2[c_out];
#pragma unroll
    for (int it = 0; it < 4; it++) {
        float mx = fmaxf(fmaxf(acc[it][0], acc[it][1]), fmaxf(acc[it][2], acc[it][3]));
        float v = mx + bias;
        g_h2[b * 1024 + c_out * 16 + it * 4 + pbase] = v > 0.f ? v : 0.f;
    }
}

// ---------------- FC1: (4096,1024) @ (512,1024)^T + b3, relu ---------------------
__global__ __launch_bounds__(256) void fc1_kernel(const float* __restrict__ b3)
{
    __shared__ float As[64][17];
    __shared__ float Bs[64][17];
    int tid = threadIdx.x;
    int tx = tid & 15, ty = tid >> 4;
    int rowBase = blockIdx.y * 64;   // batch
    int colBase = blockIdx.x * 64;   // out unit
    float acc[4][4];
#pragma unroll
    for (int i = 0; i < 4; i++)
#pragma unroll
        for (int j = 0; j < 4; j++) acc[i][j] = 0.f;

    for (int k0 = 0; k0 < 1024; k0 += 16) {
#pragma unroll
        for (int l = 0; l < 4; l++) {
            int e = tid + l * 256;
            int r = e >> 4, c = e & 15;
            As[r][c] = g_h2[(rowBase + r) * 1024 + k0 + c];
            Bs[r][c] = g_W3[(colBase + r) * 1024 + k0 + c];
        }
        __syncthreads();
#pragma unroll
        for (int kk = 0; kk < 16; kk++) {
            float a[4], bb[4];
#pragma unroll
            for (int i = 0; i < 4; i++) a[i] = As[ty * 4 + i][kk];
#pragma unroll
            for (int j = 0; j < 4; j++) bb[j] = Bs[tx * 4 + j][kk];
#pragma unroll
            for (int i = 0; i < 4; i++)
#pragma unroll
                for (int j = 0; j < 4; j++) acc[i][j] = fmaf(a[i], bb[j], acc[i][j]);
        }
        __syncthreads();
    }

#pragma unroll
    for (int i = 0; i < 4; i++) {
        int row = rowBase + ty * 4 + i;
#pragma unroll
        for (int j = 0; j < 4; j++) {
            int col = colBase + tx * 4 + j;
            float v = acc[i][j] + b3[col];
            g_h3[row * 512 + col] = v > 0.f ? v : 0.f;
        }
    }
}

// ---------------- FC2 + log_softmax ----------------------------------------------
__global__ __launch_bounds__(128) void fc2_kernel(const float* __restrict__ fw,
                                                  const float* __restrict__ fb,
                                                  float* __restrict__ out)
{
    int warp = threadIdx.x >> 5, lane = threadIdx.x & 31;
    int b = blockIdx.x * 4 + warp;
    float acc[10];
#pragma unroll
    for (int o = 0; o < 10; o++) acc[o] = 0.f;
    const float* hrow = g_h3 + b * 512;
    for (int k = lane; k < 512; k += 32) {
        float h = hrow[k];
#pragma unroll
        for (int o = 0; o < 10; o++) acc[o] = fmaf(h, fw[o * 512 + k], acc[o]);
    }
#pragma unroll
    for (int o = 0; o < 10; o++) {
        acc[o] += __shfl_xor_sync(0xffffffffu, acc[o], 16);
        acc[o] += __shfl_xor_sync(0xffffffffu, acc[o], 8);
        acc[o] += __shfl_xor_sync(0xffffffffu, acc[o], 4);
        acc[o] += __shfl_xor_sync(0xffffffffu, acc[o], 2);
        acc[o] += __shfl_xor_sync(0xffffffffu, acc[o], 1);
        acc[o] += fb[o];
    }
    if (lane == 0) {
        float m = acc[0];
#pragma unroll
        for (int o = 1; o < 10; o++) m = fmaxf(m, acc[o]);
        float s = 0.f;
#pragma unroll
        for (int o = 0; o < 10; o++) s += expf(acc[o] - m);
        float lse = m + logf(s);
#pragma unroll
        for (int o = 0; o < 10; o++) out[b * 10 + o] = acc[o] - lse;
    }
}

// ---------------- launch -----------------------------------------------------------
extern "C" void kernel_launch(void* const* d_in, const int* in_sizes, int n_in,
                              void* d_out, int out_size)
{
    const float* x  = (const float*)d_in[0];
    const int*  hi1 = (const int*)d_in[1];
    const int*  hi2 = (const int*)d_in[2];
    const int*  hi3 = (const int*)d_in[3];
    const float* s1 = (const float*)d_in[4];
    const float* s2 = (const float*)d_in[5];
    const float* s3 = (const float*)d_in[6];
    const float* w1 = (const float*)d_in[7];
    const float* b1 = (const float*)d_in[8];
    const float* w2 = (const float*)d_in[9];
    const float* b2 = (const float*)d_in[10];
    const float* w3 = (const float*)d_in[11];
    const float* b3 = (const float*)d_in[12];
    const float* fw = (const float*)d_in[13];
    const float* fb = (const float*)d_in[14];
    float* out = (float*)d_out;

    build_weights<<<(576288 + 255) / 256, 256>>>(hi1, hi2, hi3, s1, s2, s3, w1, w2, w3);
    conv1_kernel<<<BATCH, 256>>>(x, b1);
    conv2_kernel<<<BATCH, 256>>>(b2);
    fc1_kernel<<<dim3(8, 64), 256>>>(b3);
    fc2_kernel<<<BATCH / 4, 128>>>(fw, fb, out);
}

// round 3
// speedup vs baseline: 1.1248x; 1.1248x over previous
#include <cuda_runtime.h>

#define QSZ 128
#define BATCH 4096
typedef unsigned long long ull;

// ---------------- f32x2 packed-FMA helpers (ptxas never emits these from C++) ----
__device__ __forceinline__ ull pack2(float lo, float hi) {
    ull r; asm("mov.b64 %0, {%1, %2};" : "=l"(r) : "f"(lo), "f"(hi)); return r;
}
__device__ __forceinline__ void fma2(ull& d, ull a, ull b) {
    asm("fma.rn.f32x2 %0, %1, %2, %0;" : "+l"(d) : "l"(a), "l"(b));
}
__device__ __forceinline__ void unpack2(ull v, float& lo, float& hi) {
    asm("mov.b64 {%0, %1}, %2;" : "=f"(lo), "=f"(hi) : "l"(v));
}

// ---------------- scratch (static device globals; no runtime allocation) ---------
__device__ float g_wc1[25 * 32];              // [m][o]      (o-pairs adjacent)
__device__ float g_wc2[32 * 25 * 64];         // [ci][m][o]  (o-pairs adjacent)
__device__ float g_W3 [512 * 1024];           // [o][k]
__device__ float g_h1 [BATCH * 32 * 144];     // conv1 pooled+relu  [b][c][12*12]
__device__ float g_h2 [BATCH * 1024];         // conv2 pooled+relu  [b][c*16+py*4+px]
__device__ float g_h3 [BATCH * 512];          // fc1 relu

// ---------------- weight reconstruction (gather + sign) --------------------------
__global__ void build_weights(const int* __restrict__ hi1, const int* __restrict__ hi2,
                              const int* __restrict__ hi3,
                              const float* __restrict__ s1, const float* __restrict__ s2,
                              const float* __restrict__ s3,
                              const float* __restrict__ w1, const float* __restrict__ w2,
                              const float* __restrict__ w3)
{
    int idx = blockIdx.x * blockDim.x + threadIdx.x;
    if (idx < 800) {
        int m = idx >> 5, o = idx & 31;                    // [m][o]
        g_wc1[idx] = w1[o * QSZ + hi1[m]] * s1[m];
    } else if (idx < 52000) {
        int j = idx - 800;
        int ci = j / 1600, r = j % 1600;
        int m = r >> 6, o = r & 63;                        // [ci][m][o]
        int s = ci * 25 + m;                               // source into (64,800) reshape
        g_wc2[j] = w2[o * QSZ + hi2[s]] * s2[s];
    } else if (idx < 52000 + 512 * 1024) {
        int j = idx - 52000;
        int o = j >> 10, k = j & 1023;
        g_W3[j] = w3[o * QSZ + hi3[k]] * s3[k];
    }
}

// ---------------- conv1 5x5 (1->32) + maxpool2 + relu, f32x2 over channel pairs --
__global__ __launch_bounds__(256) void conv1_kernel(const float* __restrict__ x,
                                                    const float* __restrict__ b1)
{
    __shared__ float xs[784];
    __shared__ float ws[800];          // [m][o]
    int b = blockIdx.x;
    int tid = threadIdx.x;
    for (int t = tid; t < 784; t += 256) xs[t] = x[b * 784 + t];
    for (int t = tid; t < 800; t += 256) ws[t] = g_wc1[t];
    __syncthreads();

    int cp = tid & 15, slot = tid >> 4;
    int co = cp * 2;
    ull w[25];
#pragma unroll
    for (int m = 0; m < 25; m++) w[m] = *(const ull*)&ws[m * 32 + co];
    float bias0 = b1[co], bias1 = b1[co + 1];

#pragma unroll 1
    for (int it = 0; it < 9; it++) {
        int pos = slot + it * 16;               // 0..143
        int py = pos / 12, px = pos % 12;
        int r0 = 2 * py, c0 = 2 * px;
        ull acc[4] = {0ull, 0ull, 0ull, 0ull};  // [dy*2+dx], packed (co, co+1)
#pragma unroll
        for (int rr = 0; rr < 6; rr++) {
            ull prow[6];
#pragma unroll
            for (int cc = 0; cc < 6; cc++) {
                float v = xs[(r0 + rr) * 28 + c0 + cc];
                prow[cc] = pack2(v, v);
            }
#pragma unroll
            for (int dy = 0; dy < 2; dy++) {
                int ky = rr - dy;
                if (ky >= 0 && ky < 5) {
#pragma unroll
                    for (int dx = 0; dx < 2; dx++)
#pragma unroll
                        for (int kx = 0; kx < 5; kx++)
                            fma2(acc[dy * 2 + dx], prow[dx + kx], w[ky * 5 + kx]);
                }
            }
        }
        float lo[4], hi[4];
#pragma unroll
        for (int i = 0; i < 4; i++) unpack2(acc[i], lo[i], hi[i]);
        float m0 = fmaxf(fmaxf(lo[0], lo[1]), fmaxf(lo[2], lo[3])) + bias0;
        float m1 = fmaxf(fmaxf(hi[0], hi[1]), fmaxf(hi[2], hi[3])) + bias1;
        g_h1[b * 4608 + co * 144 + pos]       = m0 > 0.f ? m0 : 0.f;
        g_h1[b * 4608 + (co + 1) * 144 + pos] = m1 > 0.f ? m1 : 0.f;
    }
}

// ---------------- conv2 5x5 (32->64) + maxpool2 + relu, f32x2 over channel pairs -
// warp = one pooled position pair (input reads broadcast), lane = channel pair.
__global__ __launch_bounds__(256) void conv2_kernel(const float* __restrict__ b2)
{
    __shared__ float in_s[4608];    // 32 x 12 x 12
    __shared__ float ws[1600];      // [m][o], one ci slice
    int b = blockIdx.x;
    int tid = threadIdx.x;
    for (int t = tid; t < 4608; t += 256) in_s[t] = g_h1[b * 4608 + t];

    int cp = tid & 31, posid = tid >> 5;     // warp-uniform posid
    int co = cp * 2;
    ull acc[2][4];                           // [pos][dy*2+dx], packed (co, co+1)
#pragma unroll
    for (int i = 0; i < 2; i++)
#pragma unroll
        for (int j = 0; j < 4; j++) acc[i][j] = 0ull;

#pragma unroll 1
    for (int ci = 0; ci < 32; ci++) {
        __syncthreads();
#pragma unroll
        for (int t = 0; t < 7; t++) {
            int e = tid + t * 256;
            if (e < 1600) ws[e] = g_wc2[ci * 1600 + e];
        }
        __syncthreads();

        ull w[25];
#pragma unroll
        for (int m = 0; m < 25; m++) w[m] = *(const ull*)&ws[m * 64 + co];
        const float* in_ci = in_s + ci * 144;

#pragma unroll
        for (int pi = 0; pi < 2; pi++) {
            int pos = posid + pi * 8;        // 0..15
            int py = pos >> 2, px = pos & 3;
            int r0 = 2 * py, c0 = 2 * px;
#pragma unroll
            for (int rr = 0; rr < 6; rr++) {
                ull prow[6];
#pragma unroll
                for (int cc = 0; cc < 6; cc++) {
                    float v = in_ci[(r0 + rr) * 12 + c0 + cc];
                    prow[cc] = pack2(v, v);
                }
#pragma unroll
                for (int dy = 0; dy < 2; dy++) {
                    int ky = rr - dy;
                    if (ky >= 0 && ky < 5) {
#pragma unroll
                        for (int dx = 0; dx < 2; dx++)
#pragma unroll
                            for (int kx = 0; kx < 5; kx++)
                                fma2(acc[pi][dy * 2 + dx], prow[dx + kx], w[ky * 5 + kx]);
                    }
                }
            }
        }
    }

    float bias0 = b2[co], bias1 = b2[co + 1];
#pragma unroll
    for (int pi = 0; pi < 2; pi++) {
        int pos = posid + pi * 8;
        float lo[4], hi[4];
#pragma unroll
        for (int i = 0; i < 4; i++) unpack2(acc[pi][i], lo[i], hi[i]);
        float m0 = fmaxf(fmaxf(lo[0], lo[1]), fmaxf(lo[2], lo[3])) + bias0;
        float m1 = fmaxf(fmaxf(hi[0], hi[1]), fmaxf(hi[2], hi[3])) + bias1;
        g_h2[b * 1024 + co * 16 + pos]       = m0 > 0.f ? m0 : 0.f;
        g_h2[b * 1024 + (co + 1) * 16 + pos] = m1 > 0.f ? m1 : 0.f;
    }
}

// ---------------- FC1: (4096,1024) @ (512,1024)^T + b3, relu ---------------------
// BM=128, BN=64, TM=8, TN=4, BK=16. k-major smem tiles, float4 fragments, f32x2.
__global__ __launch_bounds__(256) void fc1_kernel(const float* __restrict__ b3)
{
    __shared__ float As[16][128];   // [k][m]
    __shared__ float Bs[16][64];    // [k][n]
    int tid = threadIdx.x;
    int tx = tid & 15, ty = tid >> 4;
    int rowBase = blockIdx.y * 128;
    int colBase = blockIdx.x * 64;

    ull acc[8][2];                  // [i][j-pair]
#pragma unroll
    for (int i = 0; i < 8; i++) { acc[i][0] = 0ull; acc[i][1] = 0ull; }

#pragma unroll 1
    for (int k0 = 0; k0 < 1024; k0 += 16) {
#pragma unroll
        for (int l = 0; l < 2; l++) {
            int e = tid + l * 256;
            int c4 = e >> 7, row = e & 127;
            float4 v = *(const float4*)&g_h2[(rowBase + row) * 1024 + k0 + c4 * 4];
            As[c4 * 4 + 0][row] = v.x;
            As[c4 * 4 + 1][row] = v.y;
            As[c4 * 4 + 2][row] = v.z;
            As[c4 * 4 + 3][row] = v.w;
        }
        {
            int c4 = tid >> 6, row = tid & 63;
            float4 v = *(const float4*)&g_W3[(colBase + row) * 1024 + k0 + c4 * 4];
            Bs[c4 * 4 + 0][row] = v.x;
            Bs[c4 * 4 + 1][row] = v.y;
            Bs[c4 * 4 + 2][row] = v.z;
            Bs[c4 * 4 + 3][row] = v.w;
        }
        __syncthreads();
#pragma unroll
        for (int kk = 0; kk < 16; kk++) {
            float4 a0 = *(const float4*)&As[kk][ty * 8];
            float4 a1 = *(const float4*)&As[kk][ty * 8 + 4];
            float4 bv = *(const float4*)&Bs[kk][tx * 4];
            ull bp0 = pack2(bv.x, bv.y);
            ull bp1 = pack2(bv.z, bv.w);
            float av[8] = {a0.x, a0.y, a0.z, a0.w, a1.x, a1.y, a1.z, a1.w};
#pragma unroll
            for (int i = 0; i < 8; i++) {
                ull as = pack2(av[i], av[i]);
                fma2(acc[i][0], as, bp0);
                fma2(acc[i][1], as, bp1);
            }
        }
        __syncthreads();
    }

    float bb0 = b3[colBase + tx * 4 + 0];
    float bb1 = b3[colBase + tx * 4 + 1];
    float bb2 = b3[colBase + tx * 4 + 2];
    float bb3 = b3[colBase + tx * 4 + 3];
#pragma unroll
    for (int i = 0; i < 8; i++) {
        int row = rowBase + ty * 8 + i;
        float v0, v1, v2, v3;
        unpack2(acc[i][0], v0, v1);
        unpack2(acc[i][1], v2, v3);
        v0 += bb0; v1 += bb1; v2 += bb2; v3 += bb3;
        float4 o;
        o.x = v0 > 0.f ? v0 : 0.f;
        o.y = v1 > 0.f ? v1 : 0.f;
        o.z = v2 > 0.f ? v2 : 0.f;
        o.w = v3 > 0.f ? v3 : 0.f;
        *(float4*)&g_h3[row * 512 + colBase + tx * 4] = o;
    }
}

// ---------------- FC2 + log_softmax ----------------------------------------------
__global__ __launch_bounds__(128) void fc2_kernel(const float* __restrict__ fw,
                                                  const float* __restrict__ fb,
                                                  float* __restrict__ out)
{
    int warp = threadIdx.x >> 5, lane = threadIdx.x & 31;
    int b = blockIdx.x * 4 + warp;
    float acc[10];
#pragma unroll
    for (int o = 0; o < 10; o++) acc[o] = 0.f;
    const float* hrow = g_h3 + b * 512;
    for (int k = lane; k < 512; k += 32) {
        float h = hrow[k];
#pragma unroll
        for (int o = 0; o < 10; o++) acc[o] = fmaf(h, fw[o * 512 + k], acc[o]);
    }
#pragma unroll
    for (int o = 0; o < 10; o++) {
        acc[o] += __shfl_xor_sync(0xffffffffu, acc[o], 16);
        acc[o] += __shfl_xor_sync(0xffffffffu, acc[o], 8);
        acc[o] += __shfl_xor_sync(0xffffffffu, acc[o], 4);
        acc[o] += __shfl_xor_sync(0xffffffffu, acc[o], 2);
        acc[o] += __shfl_xor_sync(0xffffffffu, acc[o], 1);
        acc[o] += fb[o];
    }
    if (lane == 0) {
        float m = acc[0];
#pragma unroll
        for (int o = 1; o < 10; o++) m = fmaxf(m, acc[o]);
        float s = 0.f;
#pragma unroll
        for (int o = 0; o < 10; o++) s += expf(acc[o] - m);
        float lse = m + logf(s);
#pragma unroll
        for (int o = 0; o < 10; o++) out[b * 10 + o] = acc[o] - lse;
    }
}

// ---------------- launch -----------------------------------------------------------
extern "C" void kernel_launch(void* const* d_in, const int* in_sizes, int n_in,
                              void* d_out, int out_size)
{
    const float* x  = (const float*)d_in[0];
    const int*  hi1 = (const int*)d_in[1];
    const int*  hi2 = (const int*)d_in[2];
    const int*  hi3 = (const int*)d_in[3];
    const float* s1 = (const float*)d_in[4];
    const float* s2 = (const float*)d_in[5];
    const float* s3 = (const float*)d_in[6];
    const float* w1 = (const float*)d_in[7];
    const float* b1 = (const float*)d_in[8];
    const float* w2 = (const float*)d_in[9];
    const float* b2 = (const float*)d_in[10];
    const float* w3 = (const float*)d_in[11];
    const float* b3 = (const float*)d_in[12];
    const float* fw = (const float*)d_in[13];
    const float* fb = (const float*)d_in[14];
    float* out = (float*)d_out;

    build_weights<<<(576288 + 255) / 256, 256>>>(hi1, hi2, hi3, s1, s2, s3, w1, w2, w3);
    conv1_kernel<<<BATCH, 256>>>(x, b1);
    conv2_kernel<<<BATCH, 256>>>(b2);
    fc1_kernel<<<dim3(8, 32), 256>>>(b3);
    fc2_kernel<<<BATCH / 4, 128>>>(fw, fb, out);
}

// round 5
// speedup vs baseline: 2.2904x; 2.0364x over previous
#include <cuda_runtime.h>
#include <cuda_bf16.h>
#include <cstdint>

#define QSZ 128
#define BATCH 4096
typedef unsigned long long ull;

// ---------------- f32x2 packed-FMA helpers (conv1) -------------------------------
__device__ __forceinline__ ull pack2(float lo, float hi) {
    ull r; asm("mov.b64 %0, {%1, %2};" : "=l"(r) : "f"(lo), "f"(hi)); return r;
}
__device__ __forceinline__ void fma2(ull& d, ull a, ull b) {
    asm("fma.rn.f32x2 %0, %1, %2, %0;" : "+l"(d) : "l"(a), "l"(b));
}
__device__ __forceinline__ void unpack2(ull v, float& lo, float& hi) {
    asm("mov.b64 {%0, %1}, %2;" : "=f"(lo), "=f"(hi) : "l"(v));
}

// ---------------- mma.sync / ldmatrix helpers (sm_80+ generic PTX) ---------------
__device__ __forceinline__ uint32_t smem_u32(const void* p) {
    uint32_t a;
    asm("{ .reg .u64 t; cvta.to.shared.u64 t, %1; cvt.u32.u64 %0, t; }" : "=r"(a) : "l"(p));
    return a;
}
__device__ __forceinline__ void ldsm4(uint32_t* r, uint32_t addr) {
    asm volatile("ldmatrix.sync.aligned.m8n8.x4.shared.b16 {%0,%1,%2,%3}, [%4];"
                 : "=r"(r[0]), "=r"(r[1]), "=r"(r[2]), "=r"(r[3]) : "r"(addr));
}
__device__ __forceinline__ void mma_bf16(float* d, const uint32_t* a, const uint32_t* b) {
    asm volatile("mma.sync.aligned.m16n8k16.row.col.f32.bf16.bf16.f32 "
                 "{%0,%1,%2,%3}, {%4,%5,%6,%7}, {%8,%9}, {%0,%1,%2,%3};"
                 : "+f"(d[0]), "+f"(d[1]), "+f"(d[2]), "+f"(d[3])
                 : "r"(a[0]), "r"(a[1]), "r"(a[2]), "r"(a[3]), "r"(b[0]), "r"(b[1]));
}
// per-lane smem offsets within a [rows][32 bf16 payload + 8 pad] (80B-stride) tile
__device__ __forceinline__ uint32_t laneA_off(int l) {   // A-frag ldmatrix.x4
    return (uint32_t)(((l & 7) + (((l >> 3) & 1) << 3)) * 80 + ((l >> 4) << 4));
}
__device__ __forceinline__ uint32_t laneB_off(int l) {   // B-frag ldmatrix.x4
    return (uint32_t)((((l & 7) + ((l >> 4) << 3)) * 80) + (((l >> 3) & 1) << 4));
}
// conv2 A is im2col-by-address: row = oy*12+ox; lane part of that mapping:
__device__ __forceinline__ uint32_t laneA_off_c2(int l) {
    return (uint32_t)(((((l >> 3) & 1) * 12 + (l & 7)) * 80) + ((l >> 4) << 4));
}

// ---------------- scratch (static device globals) --------------------------------
__device__ __align__(16) float g_wc1[25 * 32];                      // conv1 [m][o]
__device__ __align__(16) __nv_bfloat16 g_w2bh[25 * 64 * 40];        // [m][co][ci(+pad)]
__device__ __align__(16) __nv_bfloat16 g_w2bl[25 * 64 * 40];
__device__ __align__(16) __nv_bfloat16 g_W3h[512 * 1024];           // [n][k'] permuted
__device__ __align__(16) __nv_bfloat16 g_W3l[512 * 1024];
__device__ __align__(16) __nv_bfloat16 g_h1th[BATCH * 144 * 40];    // [b][pos][ci(+pad)]
__device__ __align__(16) __nv_bfloat16 g_h1tl[BATCH * 144 * 40];
__device__ __align__(16) __nv_bfloat16 g_h2h[BATCH * 1024];         // [b][pos*64+co]
__device__ __align__(16) __nv_bfloat16 g_h2l[BATCH * 1024];
__device__ __align__(16) float g_h3[BATCH * 512];

// ---------------- weight reconstruction (gather + sign + bf16 split) -------------
__global__ void build_weights(const int* __restrict__ hi1, const int* __restrict__ hi2,
                              const int* __restrict__ hi3,
                              const float* __restrict__ s1, const float* __restrict__ s2,
                              const float* __restrict__ s3,
                              const float* __restrict__ w1, const float* __restrict__ w2,
                              const float* __restrict__ w3)
{
    int idx = blockIdx.x * blockDim.x + threadIdx.x;
    if (idx < 800) {
        int m = idx >> 5, o = idx & 31;
        g_wc1[idx] = w1[o * QSZ + hi1[m]] * s1[m];
    } else if (idx < 64800) {
        int j = idx - 800;
        int m = j / 2560, r = j % 2560;
        int co = r / 40, ci = r % 40;
        float v = 0.f;
        if (ci < 32) {
            int s = ci * 25 + m;
            v = w2[co * QSZ + hi2[s]] * s2[s];
        }
        __nv_bfloat16 h = __float2bfloat16(v);
        g_w2bh[j] = h;
        g_w2bl[j] = __float2bfloat16(v - __bfloat162float(h));
    } else if (idx < 64800 + 512 * 1024) {
        int j = idx - 64800;
        int n = j >> 10, kp = j & 1023;
        int pos = kp >> 6, co = kp & 63;
        int k = co * 16 + pos;                   // reference hash order
        float v = w3[n * QSZ + hi3[k]] * s3[k];
        __nv_bfloat16 h = __float2bfloat16(v);
        g_W3h[j] = h;
        g_W3l[j] = __float2bfloat16(v - __bfloat162float(h));
    }
}

// ---------------- conv1 5x5 (1->32) + maxpool2 + relu, f32x2; pos-major bf16 out -
__global__ __launch_bounds__(256) void conv1_kernel(const float* __restrict__ x,
                                                    const float* __restrict__ b1)
{
    __shared__ float xs[784];
    __shared__ float ws[800];
    int b = blockIdx.x;
    int tid = threadIdx.x;
    for (int t = tid; t < 784; t += 256) xs[t] = x[b * 784 + t];
    for (int t = tid; t < 800; t += 256) ws[t] = g_wc1[t];
    __syncthreads();

    int cp = tid & 15, slot = tid >> 4;
    int co = cp * 2;
    ull w[25];
#pragma unroll
    for (int m = 0; m < 25; m++) w[m] = *(const ull*)&ws[m * 32 + co];
    float bias0 = b1[co], bias1 = b1[co + 1];

#pragma unroll 1
    for (int it = 0; it < 9; it++) {
        int pos = slot + it * 16;
        int py = pos / 12, px = pos % 12;
        int r0 = 2 * py, c0 = 2 * px;
        ull acc[4] = {0ull, 0ull, 0ull, 0ull};
#pragma unroll
        for (int rr = 0; rr < 6; rr++) {
            ull prow[6];
#pragma unroll
            for (int cc = 0; cc < 6; cc++) {
                float v = xs[(r0 + rr) * 28 + c0 + cc];
                prow[cc] = pack2(v, v);
            }
#pragma unroll
            for (int dy = 0; dy < 2; dy++) {
                int ky = rr - dy;
                if (ky >= 0 && ky < 5) {
#pragma unroll
                    for (int dx = 0; dx < 2; dx++)
#pragma unroll
                        for (int kx = 0; kx < 5; kx++)
                            fma2(acc[dy * 2 + dx], prow[dx + kx], w[ky * 5 + kx]);
                }
            }
        }
        float lo[4], hi[4];
#pragma unroll
        for (int i = 0; i < 4; i++) unpack2(acc[i], lo[i], hi[i]);
        float m0 = fmaxf(fmaxf(lo[0], lo[1]), fmaxf(lo[2], lo[3])) + bias0;
        float m1 = fmaxf(fmaxf(hi[0], hi[1]), fmaxf(hi[2], hi[3])) + bias1;
        float v0 = m0 > 0.f ? m0 : 0.f;
        float v1 = m1 > 0.f ? m1 : 0.f;
        __nv_bfloat16 h0 = __float2bfloat16(v0);
        __nv_bfloat16 h1 = __float2bfloat16(v1);
        __nv_bfloat16 l0 = __float2bfloat16(v0 - __bfloat162float(h0));
        __nv_bfloat16 l1 = __float2bfloat16(v1 - __bfloat162float(h1));
        int i0 = b * 5760 + pos * 40 + co;      // pos-major, 40-half rows
        *(__nv_bfloat162*)&g_h1th[i0] = __halves2bfloat162(h0, h1);
        *(__nv_bfloat162*)&g_h1tl[i0] = __halves2bfloat162(l0, l1);
    }
}

// ---------------- conv2 as 25 shifted K=32 HMMA GEMMs + in-frag maxpool ----------
// CTA: 4 images (M=256), N=64. warp: wm=img (m64 = one image's 8x8), wn = 32-co half.
#define C2_AIMG 11520                 // 144 rows * 80B
#define C2_ALO  46080                 // 4 * C2_AIMG
#define C2_B0   92160                 // B double-buffer base
#define C2_BSL  5120                  // 64 rows * 80B
#define C2_SMEM (C2_B0 + 2 * 2 * C2_BSL)   // 112640

__global__ __launch_bounds__(256) void conv2_mma(const float* __restrict__ b2)
{
    extern __shared__ char sm[];
    const uint32_t sbase = smem_u32(sm);
    const int tid = threadIdx.x, wid = tid >> 5, l = tid & 31;
    const int b0 = blockIdx.x * 4;
    const int wm = wid >> 1, wn = wid & 1;

    // stage A (4 images, hi+lo) — contiguous copy
    {
        const uint4* srcH = (const uint4*)g_h1th + (size_t)b0 * 720;
        const uint4* srcL = (const uint4*)g_h1tl + (size_t)b0 * 720;
        for (int idx = tid; idx < 2880; idx += 256) {
            *(uint4*)(sm + idx * 16)           = srcH[idx];
            *(uint4*)(sm + C2_ALO + idx * 16)  = srcL[idx];
        }
    }
    // stage B slice 0
    for (int idx = tid; idx < 640; idx += 256) {
        int arr = idx / 320, q = idx % 320;
        const uint4* src = arr ? (const uint4*)g_w2bl : (const uint4*)g_w2bh;
        *(uint4*)(sm + C2_B0 + arr * C2_BSL + q * 16) = src[q];
    }
    __syncthreads();

    float acc[4][4][4];
#pragma unroll
    for (int t = 0; t < 4; t++)
#pragma unroll
        for (int g = 0; g < 4; g++)
#pragma unroll
            for (int i = 0; i < 4; i++) acc[t][g][i] = 0.f;

    const uint32_t aBaseH = sbase + wm * C2_AIMG + laneA_off_c2(l);
    const uint32_t bBase0 = sbase + C2_B0 + wn * 2560 + laneB_off(l);

#pragma unroll 1
    for (int m = 0; m < 25; m++) {
        int buf = m & 1;
        // prefetch next B slice
        if (m < 24) {
            int mn = m + 1;
            for (int idx = tid; idx < 640; idx += 256) {
                int arr = idx / 320, q = idx % 320;
                const uint4* src = arr ? (const uint4*)g_w2bl : (const uint4*)g_w2bh;
                *(uint4*)(sm + C2_B0 + ((mn & 1) * 2 + arr) * C2_BSL + q * 16) = src[mn * 320 + q];
            }
        }
        int ky = m / 5, kx = m % 5;
        uint32_t aH = aBaseH + (uint32_t)(ky * 12 + kx) * 80;
        uint32_t bH = bBase0 + (uint32_t)buf * (2 * C2_BSL);
#pragma unroll
        for (int kh = 0; kh < 2; kh++) {
            uint32_t A_h[4][4], A_l[4][4];
#pragma unroll
            for (int t = 0; t < 4; t++) {
                ldsm4(A_h[t], aH + t * 1920 + kh * 32);
                ldsm4(A_l[t], aH + C2_ALO + t * 1920 + kh * 32);
            }
            uint32_t B_h[8], B_l[8];
#pragma unroll
            for (int p = 0; p < 2; p++) {
                ldsm4(&B_h[p * 4], bH + p * 1280 + kh * 32);
                ldsm4(&B_l[p * 4], bH + C2_BSL + p * 1280 + kh * 32);
            }
#pragma unroll
            for (int t = 0; t < 4; t++)
#pragma unroll
                for (int g = 0; g < 4; g++) {
                    mma_bf16(acc[t][g], A_h[t], &B_h[g * 2]);
                    mma_bf16(acc[t][g], A_h[t], &B_l[g * 2]);
                    mma_bf16(acc[t][g], A_l[t], &B_h[g * 2]);
                }
        }
        __syncthreads();
    }

    // epilogue: in-fragment 2x2 maxpool, bias, relu, bf16 hi/lo store (pos-major)
    int b = b0 + wm;
    int r = l >> 2, c = l & 3;
#pragma unroll
    for (int t = 0; t < 4; t++)
#pragma unroll
        for (int g = 0; g < 4; g++) {
            float v0 = fmaxf(acc[t][g][0], acc[t][g][2]);   // vertical pool (oy pair)
            float v1 = fmaxf(acc[t][g][1], acc[t][g][3]);
            float o0 = __shfl_xor_sync(0xffffffffu, v0, 4); // horizontal pool (ox pair)
            float o1 = __shfl_xor_sync(0xffffffffu, v1, 4);
            v0 = fmaxf(v0, o0);
            v1 = fmaxf(v1, o1);
            if ((r & 1) == 0) {
                int px = r >> 1;
                int co = wn * 32 + g * 8 + 2 * c;
                float a0 = v0 + b2[co];
                float a1 = v1 + b2[co + 1];
                a0 = a0 > 0.f ? a0 : 0.f;
                a1 = a1 > 0.f ? a1 : 0.f;
                __nv_bfloat16 h0 = __float2bfloat16(a0);
                __nv_bfloat16 h1 = __float2bfloat16(a1);
                __nv_bfloat16 l0 = __float2bfloat16(a0 - __bfloat162float(h0));
                __nv_bfloat16 l1 = __float2bfloat16(a1 - __bfloat162float(h1));
                int idx = b * 1024 + (t * 4 + px) * 64 + co;
                *(__nv_bfloat162*)&g_h2h[idx] = __halves2bfloat162(h0, h1);
                *(__nv_bfloat162*)&g_h2l[idx] = __halves2bfloat162(l0, l1);
            }
        }
}

// ---------------- FC1 HMMA: (4096,1024)@(512,1024)^T, bf16 3-pass ----------------
// CTA 128x128, warp 64x32, K-chunks of 32 double-buffered.
#define F1_T   10240                 // one 128x80B tile
#define F1_BUF (4 * F1_T)            // Ahi,Alo,Bhi,Blo
#define F1_SMEM (2 * F1_BUF)         // 81920

__global__ __launch_bounds__(256) void fc1_mma(const float* __restrict__ b3)
{
    extern __shared__ char sm[];
    const uint32_t sbase = smem_u32(sm);
    const int tid = threadIdx.x, wid = tid >> 5, l = tid & 31;
    const int rowBase = blockIdx.y * 128, colBase = blockIdx.x * 128;
    const int wm = wid >> 2, wn = wid & 3;

    auto stage = [&](int ch, int buf) {
        int k0 = ch * 32;
#pragma unroll
        for (int i = 0; i < 8; i++) {
            int idx = tid + i * 256;
            int arr = idx >> 9, rq = idx & 511;
            int r = rq >> 2, q = rq & 3;
            const __nv_bfloat16* src;
            if (arr == 0)      src = &g_h2h[(size_t)(rowBase + r) * 1024 + k0];
            else if (arr == 1) src = &g_h2l[(size_t)(rowBase + r) * 1024 + k0];
            else if (arr == 2) src = &g_W3h[(size_t)(colBase + r) * 1024 + k0];
            else               src = &g_W3l[(size_t)(colBase + r) * 1024 + k0];
            *(uint4*)(sm + buf * F1_BUF + arr * F1_T + r * 80 + q * 16) =
                ((const uint4*)src)[q];
        }
    };

    stage(0, 0);
    __syncthreads();

    float acc[4][4][4];
#pragma unroll
    for (int t = 0; t < 4; t++)
#pragma unroll
        for (int g = 0; g < 4; g++)
#pragma unroll
            for (int i = 0; i < 4; i++) acc[t][g][i] = 0.f;

    const uint32_t aOff = (uint32_t)(wm * 64) * 80 + laneA_off(l);
    const uint32_t bOff = (uint32_t)(wn * 32) * 80 + laneB_off(l);

#pragma unroll 1
    for (int ch = 0; ch < 32; ch++) {
        int buf = ch & 1;
        if (ch < 31) stage(ch + 1, buf ^ 1);
        uint32_t aH = sbase + buf * F1_BUF + aOff;
        uint32_t bH = sbase + buf * F1_BUF + 2 * F1_T + bOff;
#pragma unroll
        for (int kh = 0; kh < 2; kh++) {
            uint32_t A_h[4][4], A_l[4][4];
#pragma unroll
            for (int t = 0; t < 4; t++) {
                ldsm4(A_h[t], aH + t * 1280 + kh * 32);
                ldsm4(A_l[t], aH + F1_T + t * 1280 + kh * 32);
            }
            uint32_t B_h[8], B_l[8];
#pragma unroll
            for (int p = 0; p < 2; p++) {
                ldsm4(&B_h[p * 4], bH + p * 1280 + kh * 32);
                ldsm4(&B_l[p * 4], bH + F1_T + p * 1280 + kh * 32);
            }
#pragma unroll
            for (int t = 0; t < 4; t++)
#pragma unroll
                for (int g = 0; g < 4; g++) {
                    mma_bf16(acc[t][g], A_h[t], &B_h[g * 2]);
                    mma_bf16(acc[t][g], A_h[t], &B_l[g * 2]);
                    mma_bf16(acc[t][g], A_l[t], &B_h[g * 2]);
                }
        }
        __syncthreads();
    }

    // epilogue: bias + relu, fp32 stores
    int r = l >> 2, c = l & 3;
#pragma unroll
    for (int t = 0; t < 4; t++) {
        int row0 = rowBase + wm * 64 + 16 * t + r;
#pragma unroll
        for (int g = 0; g < 4; g++) {
            int col = colBase + wn * 32 + g * 8 + 2 * c;
            float bb0 = b3[col], bb1 = b3[col + 1];
            float u0 = acc[t][g][0] + bb0, u1 = acc[t][g][1] + bb1;
            float u2 = acc[t][g][2] + bb0, u3 = acc[t][g][3] + bb1;
            float2 p0 = make_float2(u0 > 0.f ? u0 : 0.f, u1 > 0.f ? u1 : 0.f);
            float2 p1 = make_float2(u2 > 0.f ? u2 : 0.f, u3 > 0.f ? u3 : 0.f);
            *(float2*)&g_h3[(size_t)row0 * 512 + col]       = p0;
            *(float2*)&g_h3[(size_t)(row0 + 8) * 512 + col] = p1;
        }
    }
}

// ---------------- FC2 + log_softmax ----------------------------------------------
__global__ __launch_bounds__(128) void fc2_kernel(const float* __restrict__ fw,
                                                  const float* __restrict__ fb,
                                                  float* __restrict__ out)
{
    int warp = threadIdx.x >> 5, lane = threadIdx.x & 31;
    int b = blockIdx.x * 4 + warp;
    float acc[10];
#pragma unroll
    for (int o = 0; o < 10; o++) acc[o] = 0.f;
    const float* hrow = g_h3 + b * 512;
    for (int k = lane; k < 512; k += 32) {
        float h = hrow[k];
#pragma unroll
        for (int o = 0; o < 10; o++) acc[o] = fmaf(h, fw[o * 512 + k], acc[o]);
    }
#pragma unroll
    for (int o = 0; o < 10; o++) {
        acc[o] += __shfl_xor_sync(0xffffffffu, acc[o], 16);
        acc[o] += __shfl_xor_sync(0xffffffffu, acc[o], 8);
        acc[o] += __shfl_xor_sync(0xffffffffu, acc[o], 4);
        acc[o] += __shfl_xor_sync(0xffffffffu, acc[o], 2);
        acc[o] += __shfl_xor_sync(0xffffffffu, acc[o], 1);
        acc[o] += fb[o];
    }
    if (lane == 0) {
        float m = acc[0];
#pragma unroll
        for (int o = 1; o < 10; o++) m = fmaxf(m, acc[o]);
        float s = 0.f;
#pragma unroll
        for (int o = 0; o < 10; o++) s += expf(acc[o] - m);
        float lse = m + logf(s);
#pragma unroll
        for (int o = 0; o < 10; o++) out[b * 10 + o] = acc[o] - lse;
    }
}

// ---------------- launch -----------------------------------------------------------
extern "C" void kernel_launch(void* const* d_in, const int* in_sizes, int n_in,
                              void* d_out, int out_size)
{
    const float* x  = (const float*)d_in[0];
    const int*  hi1 = (const int*)d_in[1];
    const int*  hi2 = (const int*)d_in[2];
    const int*  hi3 = (const int*)d_in[3];
    const float* s1 = (const float*)d_in[4];
    const float* s2 = (const float*)d_in[5];
    const float* s3 = (const float*)d_in[6];
    const float* w1 = (const float*)d_in[7];
    const float* b1 = (const float*)d_in[8];
    const float* w2 = (const float*)d_in[9];
    const float* b2 = (const float*)d_in[10];
    const float* w3 = (const float*)d_in[11];
    const float* b3 = (const float*)d_in[12];
    const float* fw = (const float*)d_in[13];
    const float* fb = (const float*)d_in[14];
    float* out = (float*)d_out;

    static int attr_done = 0;
    if (!attr_done) {
        cudaFuncSetAttribute(conv2_mma, cudaFuncAttributeMaxDynamicSharedMemorySize, C2_SMEM);
        cudaFuncSetAttribute(fc1_mma,  cudaFuncAttributeMaxDynamicSharedMemorySize, F1_SMEM);
        attr_done = 1;
    }

    build_weights<<<2302, 256>>>(hi1, hi2, hi3, s1, s2, s3, w1, w2, w3);
    conv1_kernel<<<BATCH, 256>>>(x, b1);
    conv2_mma<<<BATCH / 4, 256, C2_SMEM>>>(b2);
    fc1_mma<<<dim3(4, 32), 256, F1_SMEM>>>(b3);
    fc2_kernel<<<BATCH / 4, 128>>>(fw, fb, out);
}

// round 6
// speedup vs baseline: 2.6675x; 1.1646x over previous
#include <cuda_runtime.h>
#include <cuda_bf16.h>
#include <cstdint>

#define QSZ 128
#define BATCH 4096
typedef unsigned long long ull;

// ---------------- f32x2 packed-FMA helpers (conv1) -------------------------------
__device__ __forceinline__ ull pack2(float lo, float hi) {
    ull r; asm("mov.b64 %0, {%1, %2};" : "=l"(r) : "f"(lo), "f"(hi)); return r;
}
__device__ __forceinline__ void fma2(ull& d, ull a, ull b) {
    asm("fma.rn.f32x2 %0, %1, %2, %0;" : "+l"(d) : "l"(a), "l"(b));
}
__device__ __forceinline__ void unpack2(ull v, float& lo, float& hi) {
    asm("mov.b64 {%0, %1}, %2;" : "=f"(lo), "=f"(hi) : "l"(v));
}

// ---------------- mma.sync / ldmatrix / cp.async helpers (sm_80+ generic) --------
__device__ __forceinline__ uint32_t smem_u32(const void* p) {
    uint32_t a;
    asm("{ .reg .u64 t; cvta.to.shared.u64 t, %1; cvt.u32.u64 %0, t; }" : "=r"(a) : "l"(p));
    return a;
}
__device__ __forceinline__ void ldsm4(uint32_t* r, uint32_t addr) {
    asm volatile("ldmatrix.sync.aligned.m8n8.x4.shared.b16 {%0,%1,%2,%3}, [%4];"
                 : "=r"(r[0]), "=r"(r[1]), "=r"(r[2]), "=r"(r[3]) : "r"(addr));
}
__device__ __forceinline__ void mma_bf16(float* d, const uint32_t* a, const uint32_t* b) {
    asm volatile("mma.sync.aligned.m16n8k16.row.col.f32.bf16.bf16.f32 "
                 "{%0,%1,%2,%3}, {%4,%5,%6,%7}, {%8,%9}, {%0,%1,%2,%3};"
                 : "+f"(d[0]), "+f"(d[1]), "+f"(d[2]), "+f"(d[3])
                 : "r"(a[0]), "r"(a[1]), "r"(a[2]), "r"(a[3]), "r"(b[0]), "r"(b[1]));
}
__device__ __forceinline__ void cp16(uint32_t dst, const void* src) {
    asm volatile("cp.async.cg.shared.global [%0], [%1], 16;" :: "r"(dst), "l"(src) : "memory");
}
#define CP_COMMIT() asm volatile("cp.async.commit_group;" ::: "memory")
#define CP_WAIT0()  asm volatile("cp.async.wait_group 0;" ::: "memory")

// per-lane smem offsets within [rows][32 bf16 + 8 pad] (80B stride) tiles
__device__ __forceinline__ uint32_t laneA_off(int l) {
    return (uint32_t)(((l & 7) + (((l >> 3) & 1) << 3)) * 80 + ((l >> 4) << 4));
}
__device__ __forceinline__ uint32_t laneB_off(int l) {
    return (uint32_t)((((l & 7) + ((l >> 4) << 3)) * 80) + (((l >> 3) & 1) << 4));
}
__device__ __forceinline__ uint32_t laneA_off_c2(int l) {   // conv2 im2col-by-address
    return (uint32_t)(((((l >> 3) & 1) * 12 + (l & 7)) * 80) + ((l >> 4) << 4));
}

// ---------------- scratch (static device globals) --------------------------------
__device__ __align__(16) float g_wc1[25 * 32];
__device__ __align__(16) __nv_bfloat16 g_w2bh[25 * 64 * 40];        // [m][co][ci+pad]
__device__ __align__(16) __nv_bfloat16 g_w2bl[25 * 64 * 40];
__device__ __align__(16) __nv_bfloat16 g_W3h[512 * 1024];           // [n][k'] permuted
__device__ __align__(16) __nv_bfloat16 g_W3l[512 * 1024];
__device__ __align__(16) __nv_bfloat16 g_h1th[BATCH * 144 * 40];    // [b][pos][ci+pad]
__device__ __align__(16) __nv_bfloat16 g_h1tl[BATCH * 144 * 40];
__device__ __align__(16) __nv_bfloat16 g_h2h[BATCH * 1024];         // [b][pos*64+co]
__device__ __align__(16) __nv_bfloat16 g_h2l[BATCH * 1024];
__device__ __align__(16) float g_h3[BATCH * 512];

// ---------------- weight reconstruction ------------------------------------------
__global__ void build_weights(const int* __restrict__ hi1, const int* __restrict__ hi2,
                              const int* __restrict__ hi3,
                              const float* __restrict__ s1, const float* __restrict__ s2,
                              const float* __restrict__ s3,
                              const float* __restrict__ w1, const float* __restrict__ w2,
                              const float* __restrict__ w3)
{
    int idx = blockIdx.x * blockDim.x + threadIdx.x;
    if (idx < 800) {
        int m = idx >> 5, o = idx & 31;
        g_wc1[idx] = w1[o * QSZ + hi1[m]] * s1[m];
    } else if (idx < 64800) {
        int j = idx - 800;
        int m = j / 2560, r = j % 2560;
        int co = r / 40, ci = r % 40;
        float v = 0.f;
        if (ci < 32) {
            int s = ci * 25 + m;
            v = w2[co * QSZ + hi2[s]] * s2[s];
        }
        __nv_bfloat16 h = __float2bfloat16(v);
        g_w2bh[j] = h;
        g_w2bl[j] = __float2bfloat16(v - __bfloat162float(h));
    } else if (idx < 64800 + 512 * 1024) {
        int j = idx - 64800;
        int n = j >> 10, kp = j & 1023;
        int pos = kp >> 6, co = kp & 63;
        int k = co * 16 + pos;
        float v = w3[n * QSZ + hi3[k]] * s3[k];
        __nv_bfloat16 h = __float2bfloat16(v);
        g_W3h[j] = h;
        g_W3l[j] = __float2bfloat16(v - __bfloat162float(h));
    }
}

// ---------------- conv1 5x5 (1->32) + maxpool2 + relu, f32x2 ---------------------
__global__ __launch_bounds__(256) void conv1_kernel(const float* __restrict__ x,
                                                    const float* __restrict__ b1)
{
    __shared__ float xs[784];
    __shared__ float ws[800];
    int b = blockIdx.x;
    int tid = threadIdx.x;
    for (int t = tid; t < 784; t += 256) xs[t] = x[b * 784 + t];
    for (int t = tid; t < 800; t += 256) ws[t] = g_wc1[t];
    __syncthreads();

    int cp = tid & 15, slot = tid >> 4;
    int co = cp * 2;
    ull w[25];
#pragma unroll
    for (int m = 0; m < 25; m++) w[m] = *(const ull*)&ws[m * 32 + co];
    float bias0 = b1[co], bias1 = b1[co + 1];

#pragma unroll 1
    for (int it = 0; it < 9; it++) {
        int pos = slot + it * 16;
        int py = pos / 12, px = pos % 12;
        int r0 = 2 * py, c0 = 2 * px;
        ull acc[4] = {0ull, 0ull, 0ull, 0ull};
#pragma unroll
        for (int rr = 0; rr < 6; rr++) {
            ull prow[6];
#pragma unroll
            for (int cc = 0; cc < 6; cc++) {
                float v = xs[(r0 + rr) * 28 + c0 + cc];
                prow[cc] = pack2(v, v);
            }
#pragma unroll
            for (int dy = 0; dy < 2; dy++) {
                int ky = rr - dy;
                if (ky >= 0 && ky < 5) {
#pragma unroll
                    for (int dx = 0; dx < 2; dx++)
#pragma unroll
                        for (int kx = 0; kx < 5; kx++)
                            fma2(acc[dy * 2 + dx], prow[dx + kx], w[ky * 5 + kx]);
                }
            }
        }
        float lo[4], hi[4];
#pragma unroll
        for (int i = 0; i < 4; i++) unpack2(acc[i], lo[i], hi[i]);
        float m0 = fmaxf(fmaxf(lo[0], lo[1]), fmaxf(lo[2], lo[3])) + bias0;
        float m1 = fmaxf(fmaxf(hi[0], hi[1]), fmaxf(hi[2], hi[3])) + bias1;
        float v0 = m0 > 0.f ? m0 : 0.f;
        float v1 = m1 > 0.f ? m1 : 0.f;
        __nv_bfloat16 h0 = __float2bfloat16(v0);
        __nv_bfloat16 h1 = __float2bfloat16(v1);
        __nv_bfloat16 l0 = __float2bfloat16(v0 - __bfloat162float(h0));
        __nv_bfloat16 l1 = __float2bfloat16(v1 - __bfloat162float(h1));
        int i0 = b * 5760 + pos * 40 + co;
        *(__nv_bfloat162*)&g_h1th[i0] = __halves2bfloat162(h0, h1);
        *(__nv_bfloat162*)&g_h1tl[i0] = __halves2bfloat162(l0, l1);
    }
}

// ---------------- conv2: 2 images/CTA, 25 shifted K=32 HMMA GEMMs ----------------
// smem: Ahi(2 img) | Alo(2 img) | B double-buffer (hi+lo per buf)
#define C2_AIMG 11520                       // 144 rows * 80B
#define C2_ALO  23040                       // lo base
#define C2_B0   46080
#define C2_BSL  5120                        // 64 rows * 80B
#define C2_SMEM (C2_B0 + 4 * C2_BSL)        // 66560

__global__ __launch_bounds__(256) void conv2_mma(const float* __restrict__ b2)
{
    extern __shared__ char sm[];
    const uint32_t sbase = smem_u32(sm);
    const int tid = threadIdx.x, wid = tid >> 5, l = tid & 31;
    const int b0 = blockIdx.x * 2;
    const int wm = wid >> 1, wn = wid & 1;       // wm: img(2) x mhalf(2)
    const int img = wm >> 1, mh = wm & 1;

    // stage A (2 images, hi+lo) + B slice 0 via cp.async
    {
        const uint4* srcH = (const uint4*)g_h1th + (size_t)b0 * 720;
        const uint4* srcL = (const uint4*)g_h1tl + (size_t)b0 * 720;
        for (int idx = tid; idx < 1440; idx += 256) {
            cp16(sbase + idx * 16, srcH + idx);
            cp16(sbase + C2_ALO + idx * 16, srcL + idx);
        }
        for (int idx = tid; idx < 320; idx += 256) {
            cp16(sbase + C2_B0 + idx * 16, (const uint4*)g_w2bh + idx);
            cp16(sbase + C2_B0 + C2_BSL + idx * 16, (const uint4*)g_w2bl + idx);
        }
    }
    CP_COMMIT(); CP_WAIT0();
    __syncthreads();

    float acc[2][4][4];
#pragma unroll
    for (int t = 0; t < 2; t++)
#pragma unroll
        for (int g = 0; g < 4; g++)
#pragma unroll
            for (int i = 0; i < 4; i++) acc[t][g][i] = 0.f;

    const uint32_t aBaseH = sbase + img * C2_AIMG + mh * 2 * 1920 + laneA_off_c2(l);
    const uint32_t bBase0 = sbase + C2_B0 + wn * 2560 + laneB_off(l);

#pragma unroll 1
    for (int m = 0; m < 25; m++) {
        int buf = m & 1;
        if (m < 24) {
            int mn = m + 1;
            uint32_t bdst = sbase + C2_B0 + (mn & 1) * (2 * C2_BSL);
            for (int idx = tid; idx < 320; idx += 256) {
                cp16(bdst + idx * 16, (const uint4*)g_w2bh + mn * 320 + idx);
                cp16(bdst + C2_BSL + idx * 16, (const uint4*)g_w2bl + mn * 320 + idx);
            }
            CP_COMMIT();
        }
        int ky = m / 5, kx = m % 5;
        uint32_t aH = aBaseH + (uint32_t)(ky * 12 + kx) * 80;
        uint32_t bH = bBase0 + (uint32_t)buf * (2 * C2_BSL);
#pragma unroll
        for (int kh = 0; kh < 2; kh++) {
            uint32_t A_h[2][4], A_l[2][4];
#pragma unroll
            for (int t = 0; t < 2; t++) {
                ldsm4(A_h[t], aH + t * 1920 + kh * 32);
                ldsm4(A_l[t], aH + C2_ALO + t * 1920 + kh * 32);
            }
            uint32_t B_h[8], B_l[8];
#pragma unroll
            for (int p = 0; p < 2; p++) {
                ldsm4(&B_h[p * 4], bH + p * 1280 + kh * 32);
                ldsm4(&B_l[p * 4], bH + C2_BSL + p * 1280 + kh * 32);
            }
#pragma unroll
            for (int t = 0; t < 2; t++)
#pragma unroll
                for (int g = 0; g < 4; g++) {
                    mma_bf16(acc[t][g], A_h[t], &B_h[g * 2]);
                    mma_bf16(acc[t][g], A_h[t], &B_l[g * 2]);
                    mma_bf16(acc[t][g], A_l[t], &B_h[g * 2]);
                }
        }
        if (m < 24) CP_WAIT0();
        __syncthreads();
    }

    // epilogue: in-fragment 2x2 maxpool, bias, relu, bf16 hi/lo pos-major store
    int b = b0 + img;
    int r = l >> 2, c = l & 3;
#pragma unroll
    for (int t = 0; t < 2; t++)
#pragma unroll
        for (int g = 0; g < 4; g++) {
            float v0 = fmaxf(acc[t][g][0], acc[t][g][2]);
            float v1 = fmaxf(acc[t][g][1], acc[t][g][3]);
            float o0 = __shfl_xor_sync(0xffffffffu, v0, 4);
            float o1 = __shfl_xor_sync(0xffffffffu, v1, 4);
            v0 = fmaxf(v0, o0);
            v1 = fmaxf(v1, o1);
            if ((r & 1) == 0) {
                int px = r >> 1;
                int py = mh * 2 + t;
                int co = wn * 32 + g * 8 + 2 * c;
                float a0 = v0 + b2[co];
                float a1 = v1 + b2[co + 1];
                a0 = a0 > 0.f ? a0 : 0.f;
                a1 = a1 > 0.f ? a1 : 0.f;
                __nv_bfloat16 h0 = __float2bfloat16(a0);
                __nv_bfloat16 h1 = __float2bfloat16(a1);
                __nv_bfloat16 l0 = __float2bfloat16(a0 - __bfloat162float(h0));
                __nv_bfloat16 l1 = __float2bfloat16(a1 - __bfloat162float(h1));
                int idx = b * 1024 + (py * 4 + px) * 64 + co;
                *(__nv_bfloat162*)&g_h2h[idx] = __halves2bfloat162(h0, h1);
                *(__nv_bfloat162*)&g_h2l[idx] = __halves2bfloat162(l0, l1);
            }
        }
}

// ---------------- FC1 HMMA: CTA 64x128, cp.async double-buffer -------------------
#define F1_AT  5120                  // 64 rows * 80B
#define F1_BT  10240                 // 128 rows * 80B
#define F1_BUF 30720                 // Ah | Al | Bh | Bl
#define F1_SMEM (2 * F1_BUF)         // 61440

__global__ __launch_bounds__(256) void fc1_mma(const float* __restrict__ b3)
{
    extern __shared__ char sm[];
    const uint32_t sbase = smem_u32(sm);
    const int tid = threadIdx.x, wid = tid >> 5, l = tid & 31;
    const int rowBase = blockIdx.y * 64, colBase = blockIdx.x * 128;
    const int wm = wid >> 2, wn = wid & 3;

    auto stage = [&](int ch, int buf) {
        int k0 = ch * 32;
        uint32_t base = sbase + (uint32_t)buf * F1_BUF;
#pragma unroll
        for (int i = 0; i < 6; i++) {
            int idx = tid + i * 256;             // 0..1535
            const uint4* src; uint32_t dst;
            if (idx < 512) {
                int arr = idx >> 8, rq = idx & 255;
                int r = rq >> 2, q = rq & 3;
                const __nv_bfloat16* s = (arr ? g_h2l : g_h2h) + (size_t)(rowBase + r) * 1024 + k0;
                src = (const uint4*)s + q;
                dst = base + arr * F1_AT + r * 80 + q * 16;
            } else {
                int j = idx - 512;
                int arr = j >> 9, rq = j & 511;
                int r = rq >> 2, q = rq & 3;
                const __nv_bfloat16* s = (arr ? g_W3l : g_W3h) + (size_t)(colBase + r) * 1024 + k0;
                src = (const uint4*)s + q;
                dst = base + 2 * F1_AT + arr * F1_BT + r * 80 + q * 16;
            }
            cp16(dst, src);
        }
    };

    stage(0, 0);
    CP_COMMIT(); CP_WAIT0();
    __syncthreads();

    float acc[2][4][4];
#pragma unroll
    for (int t = 0; t < 2; t++)
#pragma unroll
        for (int g = 0; g < 4; g++)
#pragma unroll
            for (int i = 0; i < 4; i++) acc[t][g][i] = 0.f;

    const uint32_t aOff = (uint32_t)(wm * 32) * 80 + laneA_off(l);
    const uint32_t bOff = (uint32_t)(wn * 32) * 80 + laneB_off(l);

#pragma unroll 1
    for (int ch = 0; ch < 32; ch++) {
        int buf = ch & 1;
        if (ch < 31) { stage(ch + 1, buf ^ 1); CP_COMMIT(); }
        uint32_t aH = sbase + buf * F1_BUF + aOff;
        uint32_t bH = sbase + buf * F1_BUF + 2 * F1_AT + bOff;
#pragma unroll
        for (int kh = 0; kh < 2; kh++) {
            uint32_t A_h[2][4], A_l[2][4];
#pragma unroll
            for (int t = 0; t < 2; t++) {
                ldsm4(A_h[t], aH + t * 1280 + kh * 32);
                ldsm4(A_l[t], aH + F1_AT + t * 1280 + kh * 32);
            }
            uint32_t B_h[8], B_l[8];
#pragma unroll
            for (int p = 0; p < 2; p++) {
                ldsm4(&B_h[p * 4], bH + p * 1280 + kh * 32);
                ldsm4(&B_l[p * 4], bH + F1_BT + p * 1280 + kh * 32);
            }
#pragma unroll
            for (int t = 0; t < 2; t++)
#pragma unroll
                for (int g = 0; g < 4; g++) {
                    mma_bf16(acc[t][g], A_h[t], &B_h[g * 2]);
                    mma_bf16(acc[t][g], A_h[t], &B_l[g * 2]);
                    mma_bf16(acc[t][g], A_l[t], &B_h[g * 2]);
                }
        }
        if (ch < 31) CP_WAIT0();
        __syncthreads();
    }

    // epilogue: bias + relu, fp32 stores
    int r = l >> 2, c = l & 3;
#pragma unroll
    for (int t = 0; t < 2; t++) {
        int row0 = rowBase + wm * 32 + 16 * t + r;
#pragma unroll
        for (int g = 0; g < 4; g++) {
            int col = colBase + wn * 32 + g * 8 + 2 * c;
            float bb0 = b3[col], bb1 = b3[col + 1];
            float u0 = acc[t][g][0] + bb0, u1 = acc[t][g][1] + bb1;
            float u2 = acc[t][g][2] + bb0, u3 = acc[t][g][3] + bb1;
            float2 p0 = make_float2(u0 > 0.f ? u0 : 0.f, u1 > 0.f ? u1 : 0.f);
            float2 p1 = make_float2(u2 > 0.f ? u2 : 0.f, u3 > 0.f ? u3 : 0.f);
            *(float2*)&g_h3[(size_t)row0 * 512 + col]       = p0;
            *(float2*)&g_h3[(size_t)(row0 + 8) * 512 + col] = p1;
        }
    }
}

// ---------------- FC2 + log_softmax ----------------------------------------------
__global__ __launch_bounds__(128) void fc2_kernel(const float* __restrict__ fw,
                                                  const float* __restrict__ fb,
                                                  float* __restrict__ out)
{
    int warp = threadIdx.x >> 5, lane = threadIdx.x & 31;
    int b = blockIdx.x * 4 + warp;
    float acc[10];
#pragma unroll
    for (int o = 0; o < 10; o++) acc[o] = 0.f;
    const float* hrow = g_h3 + b * 512;
    for (int k = lane; k < 512; k += 32) {
        float h = hrow[k];
#pragma unroll
        for (int o = 0; o < 10; o++) acc[o] = fmaf(h, fw[o * 512 + k], acc[o]);
    }
#pragma unroll
    for (int o = 0; o < 10; o++) {
        acc[o] += __shfl_xor_sync(0xffffffffu, acc[o], 16);
        acc[o] += __shfl_xor_sync(0xffffffffu, acc[o], 8);
        acc[o] += __shfl_xor_sync(0xffffffffu, acc[o], 4);
        acc[o] += __shfl_xor_sync(0xffffffffu, acc[o], 2);
        acc[o] += __shfl_xor_sync(0xffffffffu, acc[o], 1);
        acc[o] += fb[o];
    }
    if (lane == 0) {
        float m = acc[0];
#pragma unroll
        for (int o = 1; o < 10; o++) m = fmaxf(m, acc[o]);
        float s = 0.f;
#pragma unroll
        for (int o = 0; o < 10; o++) s += expf(acc[o] - m);
        float lse = m + logf(s);
#pragma unroll
        for (int o = 0; o < 10; o++) out[b * 10 + o] = acc[o] - lse;
    }
}

// ---------------- launch -----------------------------------------------------------
extern "C" void kernel_launch(void* const* d_in, const int* in_sizes, int n_in,
                              void* d_out, int out_size)
{
    const float* x  = (const float*)d_in[0];
    const int*  hi1 = (const int*)d_in[1];
    const int*  hi2 = (const int*)d_in[2];
    const int*  hi3 = (const int*)d_in[3];
    const float* s1 = (const float*)d_in[4];
    const float* s2 = (const float*)d_in[5];
    const float* s3 = (const float*)d_in[6];
    const float* w1 = (const float*)d_in[7];
    const float* b1 = (const float*)d_in[8];
    const float* w2 = (const float*)d_in[9];
    const float* b2 = (const float*)d_in[10];
    const float* w3 = (const float*)d_in[11];
    const float* b3 = (const float*)d_in[12];
    const float* fw = (const float*)d_in[13];
    const float* fb = (const float*)d_in[14];
    float* out = (float*)d_out;

    static int attr_done = 0;
    if (!attr_done) {
        cudaFuncSetAttribute(conv2_mma, cudaFuncAttributeMaxDynamicSharedMemorySize, C2_SMEM);
        cudaFuncSetAttribute(fc1_mma,  cudaFuncAttributeMaxDynamicSharedMemorySize, F1_SMEM);
        attr_done = 1;
    }

    build_weights<<<2302, 256>>>(hi1, hi2, hi3, s1, s2, s3, w1, w2, w3);
    conv1_kernel<<<BATCH, 256>>>(x, b1);
    conv2_mma<<<BATCH / 2, 256, C2_SMEM>>>(b2);
    fc1_mma<<<dim3(4, 64), 256, F1_SMEM>>>(b3);
    fc2_kernel<<<BATCH / 4, 128>>>(fw, fb, out);
}